// round 16
// baseline (speedup 1.0000x reference)
#include <cuda_runtime.h>
#include <cuda_bf16.h>

#define Bv   4
#define Nv   25200
#define MAXD 100
#define NBv  5
#define ARv  14
#define MRv  56
#define ATT  (NBv*ARv*ARv)     // 980
#define PIX  (MRv*MRv)         // 3136
#define V4PD (PIX/4)           // 784 float4 per detection
#define NITEMS (Bv*MAXD*V4PD)  // 313600 total float4 items
#define NBLKW  740             // one full wave: 148 SMs x 5 CTAs
#define NTHR   (NBLKW*256)     // 189440 threads
#define L2E  1.4426950408889634f

#define OFF_BOX   4
#define OFF_SCR   (4 + Bv*MAXD*4)
#define OFF_CLS   (OFF_SCR + Bv*MAXD)
#define OFF_MSK   (OFF_CLS + Bv*MAXD)

__device__ __forceinline__ float ex2(float x) {
    float r; asm("ex2.approx.f32 %0, %1;" : "=f"(r) : "f"(x)); return r;
}
__device__ __forceinline__ float tanh_ap(float x) {
    float r; asm("tanh.approx.f32 %0, %1;" : "=f"(r) : "f"(x)); return r;
}

// R7 per-item body.
__device__ __forceinline__ void do_item(
    int t, const float* __restrict__ attn, const int* __restrict__ det_indices,
    const float* __restrict__ pooled, float* __restrict__ out)
{
    const int d  = t / V4PD;                  // detection 0..399
    const int j  = t - d * V4PD;              // item within detection 0..783
    const int b  = d / MAXD;

    const int idx = __ldg(det_indices + d);

    // Pooled: zero L1 reuse (25 MB stream) -> bypass L1, keep L2.
    const float4* pb4 = (const float4*)pooled + (size_t)d * NBv * V4PD + j;
    float4 pv0 = __ldcg(pb4);
    float4 pv1 = __ldcg(pb4 + V4PD);
    float4 pv2 = __ldcg(pb4 + 2*V4PD);
    float4 pv3 = __ldcg(pb4 + 3*V4PD);
    float4 pv4 = __ldcg(pb4 + 4*V4PD);

    const int y = j / (MRv/4);                // output row 0..55
    const int m = j - y * (MRv/4);            // float4 col group 0..13

    const float cy = y * 0.25f - 0.375f;
    const float fy = floorf(cy);
    const float wy = cy - fy;
    const int iy = (int)fy;
    const int r0 = max(0, min(ARv - 1, iy));
    const int r1 = max(0, min(ARv - 1, iy + 1));

    const int cm1 = max(m - 1, 0);
    const int cp1 = min(m + 1, ARv - 1);

    const float* ar = attn + ((size_t)b * Nv + (size_t)idx) * ATT;

    const float WL0 = 0.375f * L2E, WL1 = 0.625f * L2E;
    const float WH0 = 0.125f * L2E, WH1 = 0.875f * L2E;

    float s0 = 0.f, s1 = 0.f, s2 = 0.f, s3 = 0.f;
    float d0 = 0.f, d1 = 0.f, d2 = 0.f, d3 = 0.f;

    #pragma unroll
    for (int c = 0; c < NBv; c++) {
        const float* q0 = ar + c * (ARv*ARv) + r0 * ARv;
        const float* q1 = ar + c * (ARv*ARv) + r1 * ARv;
        float t0a = __ldg(q0 + cm1), t0b = __ldg(q0 + m), t0c = __ldg(q0 + cp1);
        float t1a = __ldg(q1 + cm1), t1b = __ldg(q1 + m), t1c = __ldg(q1 + cp1);

        float u0 = fmaf(wy, t1a - t0a, t0a);
        float u1 = fmaf(wy, t1b - t0b, t0b);
        float u2 = fmaf(wy, t1c - t0c, t0c);

        float tlo = WL1 * u1;
        float thi = WH1 * u1;
        float e0 = ex2(fmaf(WL0, u0, tlo));
        float e1 = ex2(fmaf(WH0, u0, thi));
        float e2 = ex2(fmaf(WH0, u2, thi));
        float e3 = ex2(fmaf(WL0, u2, tlo));

        float4 pv = (c == 0) ? pv0 : (c == 1) ? pv1 : (c == 2) ? pv2 : (c == 3) ? pv3 : pv4;
        s0 += e0; d0 = fmaf(e0, pv.x, d0);
        s1 += e1; d1 = fmaf(e1, pv.y, d1);
        s2 += e2; d2 = fmaf(e2, pv.z, d2);
        s3 += e3; d3 = fmaf(e3, pv.w, d3);
    }

    float4 res;
    res.x = fmaf(0.5f, tanh_ap(0.5f * __fdividef(d0, s0)), 0.5f);
    res.y = fmaf(0.5f, tanh_ap(0.5f * __fdividef(d1, s1)), 0.5f);
    res.z = fmaf(0.5f, tanh_ap(0.5f * __fdividef(d2, s2)), 0.5f);
    res.w = fmaf(0.5f, tanh_ap(0.5f * __fdividef(d3, s3)), 0.5f);

    ((float4*)(out + OFF_MSK))[t] = res;
}

__global__ __launch_bounds__(256, 5) void mask2_fused_kernel(
    const float* __restrict__ attn,
    const int*   __restrict__ num_det,
    const float* __restrict__ det_boxes,
    const float* __restrict__ det_scores,
    const int*   __restrict__ det_classes,
    const int*   __restrict__ det_indices,
    const float* __restrict__ pooled,
    float*       __restrict__ out)
{
    const int blk = blockIdx.x;
    const int t = blk * 256 + threadIdx.x;

    // One perfect wave (740 blocks = 148 SMs x 5 CTAs).
    // Blocks 0..484 do two items; 485..739 do one. Pass-through copies ride
    // on LIGHT block 739 (fills its slack instead of adding a serial tail).
    do_item(t, attn, det_indices, pooled, out);
    if (t < NITEMS - NTHR)
        do_item(t + NTHR, attn, det_indices, pooled, out);

    if (blk == NBLKW - 1) {
        int tt = threadIdx.x;
        if (tt < Bv) out[tt] = (float)num_det[tt];
        const float4* bx4 = (const float4*)det_boxes;
        float4* ob4 = (float4*)(out + OFF_BOX);
        for (int i = tt; i < Bv*MAXD; i += 256) ob4[i] = bx4[i];
        const float4* sc4 = (const float4*)det_scores;
        float4* os4 = (float4*)(out + OFF_SCR);
        for (int i = tt; i < Bv*MAXD/4; i += 256) os4[i] = sc4[i];
        for (int i = tt; i < Bv*MAXD; i += 256) out[OFF_CLS + i] = (float)det_classes[i];
    }
}

extern "C" void kernel_launch(void* const* d_in, const int* in_sizes, int n_in,
                              void* d_out, int out_size) {
    const float* attn        = (const float*)d_in[1];
    const int*   num_det     = (const int*)  d_in[3];
    const float* det_boxes   = (const float*)d_in[4];
    const float* det_scores  = (const float*)d_in[5];
    const int*   det_classes = (const int*)  d_in[6];
    const int*   det_indices = (const int*)  d_in[7];
    const float* pooled      = (const float*)d_in[8];
    float* out = (float*)d_out;

    mask2_fused_kernel<<<NBLKW, 256>>>(
        attn, num_det, det_boxes, det_scores, det_classes,
        det_indices, pooled, out);
}

// round 17
// speedup vs baseline: 1.2362x; 1.2362x over previous
#include <cuda_runtime.h>
#include <cuda_bf16.h>

#define Bv   4
#define Nv   25200
#define MAXD 100
#define NBv  5
#define ARv  14
#define MRv  56
#define ATT  (NBv*ARv*ARv)     // 980
#define PIX  (MRv*MRv)         // 3136
#define V4PD (PIX/4)           // 784 float4 per detection
#define NITEMS (Bv*MAXD*V4PD)  // 313600 total float4 items
#define L2E  1.4426950408889634f

#define OFF_BOX   4
#define OFF_SCR   (4 + Bv*MAXD*4)
#define OFF_CLS   (OFF_SCR + Bv*MAXD)
#define OFF_MSK   (OFF_CLS + Bv*MAXD)

__device__ __forceinline__ float ex2(float x) {
    float r; asm("ex2.approx.f32 %0, %1;" : "=f"(r) : "f"(x)); return r;
}
__device__ __forceinline__ float tanh_ap(float x) {
    float r; asm("tanh.approx.f32 %0, %1;" : "=f"(r) : "f"(x)); return r;
}

__global__ __launch_bounds__(256, 5) void mask2_fused_kernel(
    const float* __restrict__ attn,
    const int*   __restrict__ num_det,
    const float* __restrict__ det_boxes,
    const float* __restrict__ det_scores,
    const int*   __restrict__ det_classes,
    const int*   __restrict__ det_indices,
    const float* __restrict__ pooled,
    float*       __restrict__ out)
{
    const int blk = blockIdx.x;
    if (blk == NITEMS / 256) {
        int t = threadIdx.x;
        if (t < Bv) out[t] = (float)num_det[t];
        const float4* bx4 = (const float4*)det_boxes;
        float4* ob4 = (float4*)(out + OFF_BOX);
        for (int i = t; i < Bv*MAXD; i += blockDim.x) ob4[i] = bx4[i];
        const float4* sc4 = (const float4*)det_scores;
        float4* os4 = (float4*)(out + OFF_SCR);
        for (int i = t; i < Bv*MAXD/4; i += blockDim.x) os4[i] = sc4[i];
        for (int i = t; i < Bv*MAXD; i += blockDim.x) out[OFF_CLS + i] = (float)det_classes[i];
        return;
    }

    const int t  = blk * 256 + threadIdx.x;   // 0..313599
    const int d  = t / V4PD;                  // detection 0..399
    const int j  = t - d * V4PD;              // item within detection 0..783
    const int b  = d / MAXD;

    // idx gates the tap addresses — issue it first.
    const int idx = __ldg(det_indices + d);

    // 5 independent pooled LDG.128 (coalesced).
    const float4* pb4 = (const float4*)pooled + (size_t)d * NBv * V4PD + j;
    float4 pv0 = __ldg(pb4);
    float4 pv1 = __ldg(pb4 + V4PD);
    float4 pv2 = __ldg(pb4 + 2*V4PD);
    float4 pv3 = __ldg(pb4 + 3*V4PD);
    float4 pv4 = __ldg(pb4 + 4*V4PD);

    // ---- geometry (bilinear 14->56, half-pixel centers, edge clamp) ----
    const int y = j / (MRv/4);                // output row 0..55
    const int m = j - y * (MRv/4);            // float4 col group 0..13

    const float cy = y * 0.25f - 0.375f;
    const float fy = floorf(cy);
    const float wy = cy - fy;
    const int iy = (int)fy;
    const int r0 = max(0, min(ARv - 1, iy));
    const int r1 = max(0, min(ARv - 1, iy + 1));

    const int cm1 = max(m - 1, 0);
    const int cp1 = min(m + 1, ARv - 1);

    const float* ar = attn + ((size_t)b * Nv + (size_t)idx) * ATT;

    // horizontal weights with log2(e) folded in (bilinear is linear)
    const float WL0 = 0.375f * L2E, WL1 = 0.625f * L2E;
    const float WH0 = 0.125f * L2E, WH1 = 0.875f * L2E;

    float s0 = 0.f, s1 = 0.f, s2 = 0.f, s3 = 0.f;
    float d0 = 0.f, d1 = 0.f, d2 = 0.f, d3 = 0.f;

    #pragma unroll
    for (int c = 0; c < NBv; c++) {
        const float* q0 = ar + c * (ARv*ARv) + r0 * ARv;
        const float* q1 = ar + c * (ARv*ARv) + r1 * ARv;
        float t0a = __ldg(q0 + cm1), t0b = __ldg(q0 + m), t0c = __ldg(q0 + cp1);
        float t1a = __ldg(q1 + cm1), t1b = __ldg(q1 + m), t1c = __ldg(q1 + cp1);

        float u0 = fmaf(wy, t1a - t0a, t0a);
        float u1 = fmaf(wy, t1b - t0b, t0b);
        float u2 = fmaf(wy, t1c - t0c, t0c);

        float tlo = WL1 * u1;
        float thi = WH1 * u1;
        float e0 = ex2(fmaf(WL0, u0, tlo));
        float e1 = ex2(fmaf(WH0, u0, thi));
        float e2 = ex2(fmaf(WH0, u2, thi));
        float e3 = ex2(fmaf(WL0, u2, tlo));

        float4 pv = (c == 0) ? pv0 : (c == 1) ? pv1 : (c == 2) ? pv2 : (c == 3) ? pv3 : pv4;
        s0 += e0; d0 = fmaf(e0, pv.x, d0);
        s1 += e1; d1 = fmaf(e1, pv.y, d1);
        s2 += e2; d2 = fmaf(e2, pv.z, d2);
        s3 += e3; d3 = fmaf(e3, pv.w, d3);
    }

    float4 res;
    res.x = fmaf(0.5f, tanh_ap(0.5f * __fdividef(d0, s0)), 0.5f);
    res.y = fmaf(0.5f, tanh_ap(0.5f * __fdividef(d1, s1)), 0.5f);
    res.z = fmaf(0.5f, tanh_ap(0.5f * __fdividef(d2, s2)), 0.5f);
    res.w = fmaf(0.5f, tanh_ap(0.5f * __fdividef(d3, s3)), 0.5f);

    ((float4*)(out + OFF_MSK))[t] = res;
}

extern "C" void kernel_launch(void* const* d_in, const int* in_sizes, int n_in,
                              void* d_out, int out_size) {
    const float* attn        = (const float*)d_in[1];
    const int*   num_det     = (const int*)  d_in[3];
    const float* det_boxes   = (const float*)d_in[4];
    const float* det_scores  = (const float*)d_in[5];
    const int*   det_classes = (const int*)  d_in[6];
    const int*   det_indices = (const int*)  d_in[7];
    const float* pooled      = (const float*)d_in[8];
    float* out = (float*)d_out;

    mask2_fused_kernel<<<NITEMS / 256 + 1, 256>>>(
        attn, num_det, det_boxes, det_scores, det_classes,
        det_indices, pooled, out);
}